// round 13
// baseline (speedup 1.0000x reference)
#include <cuda_runtime.h>
#include <cuda_fp16.h>
#include <cstdint>

// ---------------------------------------------------------------------------
// Problem dims
// ---------------------------------------------------------------------------
#define N_DIM  8192
#define IN_CH  128
#define OUT_CH 64

// Big-GEMM tiling
#define TM       128               // M rows per tile
#define KB       32                // K per stage (elements)
#define SPLITK   16
#define KSPAN    (N_DIM / SPLITK)  // 512
#define NITER    (KSPAN / KB)      // 16
#define GTHREADS 256               // 8 warps: 4x2 grid of 32x32 warp tiles
#define NTILES   ((N_DIM / TM) * SPLITK)   // 1024
#define PERSIST  456               // 152 SMs x 3 CTAs

// Dynamic SMEM layout:
//   F[3]  : A fp32 stages, 128B rows, 16384 B each       (0 .. 49152)
//   SB[2] : B fp16 stages, 64B swizzled rows, 4096 B each (49152 .. 57344)
#define F_STRIDE   16384
#define SB_BASE    49152
#define SB_STRIDE  4096
#define DSMEM      57344

// ---------------------------------------------------------------------------
// Scratch (__device__ globals). Referenced ONLY from device code — never
// passed as kernel args from host (that was the R4/R5 bug).
// ---------------------------------------------------------------------------
__device__ __align__(16) float g_part[SPLITK * N_DIM * OUT_CH];  // 32 MB partials
__device__ __align__(16) __half g_bf[OUT_CH * N_DIM];            // B^T fp16, K-major
__device__ int g_ctr[2];                                         // tile queues

// ---------------------------------------------------------------------------
// PTX helpers
// ---------------------------------------------------------------------------
__device__ __forceinline__ uint32_t smem_u32(const void* p) {
    uint32_t a;
    asm("{ .reg .u64 t; cvta.to.shared.u64 t, %1; cvt.u32.u64 %0, t; }"
        : "=r"(a) : "l"(p));
    return a;
}
__device__ __forceinline__ void ldsm4(uint32_t* r, uint32_t addr) {
    asm volatile("ldmatrix.sync.aligned.m8n8.x4.shared.b16 {%0,%1,%2,%3}, [%4];"
                 : "=r"(r[0]), "=r"(r[1]), "=r"(r[2]), "=r"(r[3]) : "r"(addr));
}
__device__ __forceinline__ void mma16816(float* c, const uint32_t* a,
                                         uint32_t b0, uint32_t b1) {
    asm volatile(
        "mma.sync.aligned.m16n8k16.row.col.f32.f16.f16.f32 "
        "{%0,%1,%2,%3}, {%4,%5,%6,%7}, {%8,%9}, {%0,%1,%2,%3};"
        : "+f"(c[0]), "+f"(c[1]), "+f"(c[2]), "+f"(c[3])
        : "r"(a[0]), "r"(a[1]), "r"(a[2]), "r"(a[3]), "r"(b0), "r"(b1));
}
__device__ __forceinline__ void cp16(uint32_t dst, const void* src) {
    asm volatile("cp.async.cg.shared.global [%0], [%1], 16;"
                 :: "r"(dst), "l"(src) : "memory");
}
#define CP_COMMIT() asm volatile("cp.async.commit_group;" ::: "memory")
#define CP_WAIT1()  asm volatile("cp.async.wait_group 1;"  ::: "memory")

// Build one m16k16 A fragment (fp16 packed) straight from the fp32 stage.
// Lane layout (PTX spec): a0=(r,c) a1=(r+8,c) a2=(r,c+8) a3=(r+8,c+8),
// r = lane>>2, c = (lane&3)*2; 128B rows in F.
__device__ __forceinline__ void ldfragA(uint32_t* a, const char* fb,
                                        int rowbase, int colbase,
                                        int fr, int fc) {
    const char* p0 = fb + (rowbase + fr) * 128 + (colbase + fc) * 4;
    float2 v00 = *reinterpret_cast<const float2*>(p0);
    float2 v10 = *reinterpret_cast<const float2*>(p0 + 8 * 128);
    float2 v01 = *reinterpret_cast<const float2*>(p0 + 32);
    float2 v11 = *reinterpret_cast<const float2*>(p0 + 8 * 128 + 32);
    asm("cvt.rn.f16x2.f32 %0, %1, %2;" : "=r"(a[0]) : "f"(v00.y), "f"(v00.x));
    asm("cvt.rn.f16x2.f32 %0, %1, %2;" : "=r"(a[1]) : "f"(v10.y), "f"(v10.x));
    asm("cvt.rn.f16x2.f32 %0, %1, %2;" : "=r"(a[2]) : "f"(v01.y), "f"(v01.x));
    asm("cvt.rn.f16x2.f32 %0, %1, %2;" : "=r"(a[3]) : "f"(v11.y), "f"(v11.x));
}

// ---------------------------------------------------------------------------
// Kernel 1: g_bf[n][k] = fp16( (features @ W)[k][n] ) + reset tile queues.
// ---------------------------------------------------------------------------
__global__ __launch_bounds__(256) void lin_kernel(
    const float* __restrict__ F, const float* __restrict__ W)
{
    if (blockIdx.x == 0 && threadIdx.x < 2) g_ctr[threadIdx.x] = 0;

    __shared__ float Ws[IN_CH][OUT_CH];
    const int tid = threadIdx.x;
    #pragma unroll
    for (int t = 0; t < 8; t++) {
        int idx = tid + t * 256;
        int r = idx >> 4, c4 = idx & 15;
        *reinterpret_cast<float4*>(&Ws[r][c4 * 4]) =
            *reinterpret_cast<const float4*>(&W[r * OUT_CH + c4 * 4]);
    }
    __syncthreads();

    const int row = blockIdx.x * 32 + (tid >> 3);
    const int c0  = (tid & 7) * 8;
    float acc[8];
    #pragma unroll
    for (int j = 0; j < 8; j++) acc[j] = 0.0f;

    #pragma unroll 8
    for (int k = 0; k < IN_CH; k += 4) {
        float4 a4 = *reinterpret_cast<const float4*>(&F[row * IN_CH + k]);
        float av[4] = {a4.x, a4.y, a4.z, a4.w};
        #pragma unroll
        for (int kk = 0; kk < 4; kk++)
            #pragma unroll
            for (int j = 0; j < 8; j++)
                acc[j] = fmaf(av[kk], Ws[k + kk][c0 + j], acc[j]);
    }
    #pragma unroll
    for (int j = 0; j < 8; j++)
        g_bf[(size_t)(c0 + j) * N_DIM + row] = __float2half(acc[j]);
}

// ---------------------------------------------------------------------------
// Kernel 2: fp16 GEMM, 3-deep cp.async fp32-A pipeline, direct fragment
//           conversion (no fp16 A stage), persistent CTAs.
// ---------------------------------------------------------------------------
#define ISSUE_A(it_) do {                                                       \
    uint32_t fd_ = sbase + (uint32_t)((it_) % 3) * F_STRIDE +                   \
                   (uint32_t)aR * 128 + (uint32_t)aH * 64;                      \
    _Pragma("unroll")                                                           \
    for (int j_ = 0; j_ < 4; j_++)                                              \
        cp16(fd_ + j_ * 16, Ap + (it_) * KB + j_ * 4);                          \
} while (0)

__global__ __launch_bounds__(GTHREADS, 3) void mma_gemm(
    const float* __restrict__ A, int phase)
{
    extern __shared__ __align__(128) char sm[];
    __shared__ int s_tile;
    const uint32_t sbase = smem_u32(sm);

    const int tid = threadIdx.x;
    const int wid = tid >> 5;
    const int lid = tid & 31;
    const int wRow = wid >> 1;                // rows wRow*32..+31
    const int wCol = wid & 1;                 // cols wCol*32..+31

    // A cp.async coords: row aR = tid>>1, half aH = tid&1 (16 floats)
    const int aR = tid >> 1;
    const int aH = tid & 1;
    // B staging: row = tid>>2 (0..63), 16B chunk = tid&3
    const int bRow = tid >> 2;
    const int bC   = tid & 3;
    const uint32_t bDst = (uint32_t)bRow * 64 +
                          (((uint32_t)bC ^ (uint32_t)((bRow >> 1) & 3)) << 4);

    // fragment lane coords
    const int fr = lid >> 2;
    const int fc = (lid & 3) * 2;
    const uint32_t rBL   = (uint32_t)((lid & 7) + ((lid >> 4) & 1) * 8);
    const uint32_t bFXor = (rBL >> 1) & 3u;
    const uint32_t bSel  = (uint32_t)((lid >> 3) & 1);

    for (;;) {
        if (tid == 0) s_tile = atomicAdd(&g_ctr[phase], 1);
        __syncthreads();
        const int t = s_tile;
        if (t >= NTILES) break;

        const int mBase = (t & 63) * TM;
        const int kBase = (t >> 6) * KSPAN;
        const float*  Ap = A + (size_t)(mBase + aR) * N_DIM + kBase + aH * 16;
        const __half* Bp = g_bf + (size_t)bRow * N_DIM + kBase + bC * 8;

        float acc[8][4];
        #pragma unroll
        for (int q = 0; q < 8; q++)
            #pragma unroll
            for (int j = 0; j < 4; j++) acc[q][j] = 0.0f;

        // ---- prologue: G0, G1 in flight; B[0] staged ----
        ISSUE_A(0); CP_COMMIT();
        ISSUE_A(1); CP_COMMIT();
        uint4 breg = *reinterpret_cast<const uint4*>(Bp);
        CP_WAIT1();                       // G0 complete
        *reinterpret_cast<uint4*>(sm + SB_BASE + bDst) = breg;
        __syncthreads();

        for (int it = 0; it < NITER; it++) {
            // 1. issue A for it+2 (2 iterations of slack) + prefetch B[it+1]
            if (it + 2 < NITER) ISSUE_A(it + 2);
            CP_COMMIT();                  // always commit (possibly empty)
            if (it + 1 < NITER)
                breg = *reinterpret_cast<const uint4*>(Bp + (it + 1) * KB);

            // 2. compute from F[it%3] + SB[it&1]
            const char* Fp = sm + (it % 3) * F_STRIDE;
            const uint32_t sb = sbase + SB_BASE + (uint32_t)(it & 1) * SB_STRIDE;
            #pragma unroll
            for (int ks = 0; ks < 2; ks++) {
                uint32_t a0[4], a1[4];
                ldfragA(a0, Fp, wRow * 32,      ks * 16, fr, fc);
                ldfragA(a1, Fp, wRow * 32 + 16, ks * 16, fr, fc);
                uint32_t bOff = (((uint32_t)(ks * 2) + bSel) ^ bFXor) << 4;
                #pragma unroll
                for (int bg = 0; bg < 2; bg++) {
                    uint32_t rB = (uint32_t)(wCol * 32 + bg * 16) + rBL;
                    uint32_t b[4];
                    ldsm4(b, sb + rB * 64 + bOff);
                    mma16816(acc[bg * 2],     a0, b[0], b[1]);
                    mma16816(acc[bg * 2 + 1], a0, b[2], b[3]);
                    mma16816(acc[4 + bg * 2],     a1, b[0], b[1]);
                    mma16816(acc[4 + bg * 2 + 1], a1, b[2], b[3]);
                }
            }

            // 3. retire G(it+1); stage B[it+1]; barrier
            CP_WAIT1();
            if (it + 1 < NITER)
                *reinterpret_cast<uint4*>(
                    sm + SB_BASE + ((it + 1) & 1) * SB_STRIDE + bDst) = breg;
            __syncthreads();
        }

        // ---- epilogue: write partials ----
        const int g  = lid >> 2;
        const int tg = lid & 3;
        float* part = g_part + (size_t)(t >> 6) * (N_DIM * OUT_CH);
        #pragma unroll
        for (int mg = 0; mg < 2; mg++) {
            const int row0 = mBase + wRow * 32 + mg * 16 + g;
            #pragma unroll
            for (int p = 0; p < 4; p++) {
                const float* c = acc[mg * 4 + p];
                int col = wCol * 32 + p * 8 + tg * 2;
                *reinterpret_cast<float2*>(&part[(size_t)row0 * OUT_CH + col]) =
                    make_float2(c[0], c[1]);
                *reinterpret_cast<float2*>(&part[(size_t)(row0 + 8) * OUT_CH + col]) =
                    make_float2(c[2], c[3]);
            }
        }
    }
}

// ---------------------------------------------------------------------------
// Kernel 3: reduce split-K partials.
//   phase 0: g_bf[n][m] = fp16( filt[m] * sum_s P[s][m][n] )  (fused transpose)
//   phase 1: d_out      = sum_s P[s]
// ---------------------------------------------------------------------------
__global__ __launch_bounds__(256) void reduce_kernel(
    const float* __restrict__ filt, float* __restrict__ outp, int phase)
{
    const int i = blockIdx.x * blockDim.x + threadIdx.x;
    const int stride4 = (N_DIM * OUT_CH) / 4;
    const float4* P = reinterpret_cast<const float4*>(g_part);

    float4 s = P[i];
    #pragma unroll
    for (int sp = 1; sp < SPLITK; sp++) {
        float4 v = P[i + sp * stride4];
        s.x += v.x; s.y += v.y; s.z += v.z; s.w += v.w;
    }
    if (phase == 0) {
        int m = (i * 4) / OUT_CH;
        int c = (i * 4) % OUT_CH;
        float f = filt[m];
        g_bf[(size_t)(c + 0) * N_DIM + m] = __float2half(s.x * f);
        g_bf[(size_t)(c + 1) * N_DIM + m] = __float2half(s.y * f);
        g_bf[(size_t)(c + 2) * N_DIM + m] = __float2half(s.z * f);
        g_bf[(size_t)(c + 3) * N_DIM + m] = __float2half(s.w * f);
    } else {
        reinterpret_cast<float4*>(outp)[i] = s;
    }
}

// ---------------------------------------------------------------------------
// Launch. Inputs: features, weight_matrix, filt, wavelets, wavelets_inv.
// ---------------------------------------------------------------------------
extern "C" void kernel_launch(void* const* d_in, const int* in_sizes, int n_in,
                              void* d_out, int out_size)
{
    const float* features     = (const float*)d_in[0];
    const float* weight       = (const float*)d_in[1];
    const float* filt         = (const float*)d_in[2];
    const float* wavelets     = (const float*)d_in[3];
    const float* wavelets_inv = (const float*)d_in[4];
    float* out = (float*)d_out;

    // dynamic-smem opt-in (host-side attribute, not a stream op; no guard)
    cudaFuncSetAttribute(mma_gemm,
                         cudaFuncAttributeMaxDynamicSharedMemorySize, DSMEM);

    const int redBlocks = (N_DIM * OUT_CH) / 4 / 256;   // 512

    lin_kernel<<<N_DIM / 32, 256>>>(features, weight);
    mma_gemm<<<PERSIST, GTHREADS, DSMEM>>>(wavelets_inv, 0);
    reduce_kernel<<<redBlocks, 256>>>(filt, nullptr, 0);
    mma_gemm<<<PERSIST, GTHREADS, DSMEM>>>(wavelets, 1);
    reduce_kernel<<<redBlocks, 256>>>(filt, out, 1);
}

// round 14
// speedup vs baseline: 1.5543x; 1.5543x over previous
#include <cuda_runtime.h>
#include <cuda_fp16.h>
#include <cstdint>

// ---------------------------------------------------------------------------
// Problem dims
// ---------------------------------------------------------------------------
#define N_DIM  8192
#define IN_CH  128
#define OUT_CH 64

// Big-GEMM tiling (mma.sync fp16; tcgen05 unavailable at compute_103)
#define TM       128               // M rows per tile
#define KB       32                // K per stage (fp16 elements)
#define SPLITK   16
#define KSPAN    (N_DIM / SPLITK)  // 512
#define NITER    (KSPAN / KB)      // 16
#define GTHREADS 256               // 8 warps; each warp: 16 rows x 64 cols

// Dynamic SMEM:
//   landing[2] : A fp32, per-thread 80B slots (cp.async dest, LDS.128-clean)
//   stage[2]   : fp16, 64B swizzled rows: A 8192 B | B 4096 B
#define F_STAGE   20480            // 256 * 80
#define H_BASE    40960            // 2 * F_STAGE
#define H_STRIDE  12288
#define ST_A      0
#define ST_B      8192
#define DSMEM     65536            // 40960 + 2*12288

// ---------------------------------------------------------------------------
// Scratch (__device__ globals). Referenced ONLY from device code — never
// passed as kernel args from host (that was the R4/R5 bug).
// ---------------------------------------------------------------------------
__device__ __align__(16) float g_part[SPLITK * N_DIM * OUT_CH];  // 32 MB partials
__device__ __align__(16) __half g_bf[OUT_CH * N_DIM];            // B^T fp16, K-major

// ---------------------------------------------------------------------------
// PTX helpers (baseline ISA: ldmatrix + mma.sync + cp.async)
// ---------------------------------------------------------------------------
__device__ __forceinline__ uint32_t smem_u32(const void* p) {
    uint32_t a;
    asm("{ .reg .u64 t; cvta.to.shared.u64 t, %1; cvt.u32.u64 %0, t; }"
        : "=r"(a) : "l"(p));
    return a;
}
__device__ __forceinline__ void ldsm4(uint32_t* r, uint32_t addr) {
    asm volatile("ldmatrix.sync.aligned.m8n8.x4.shared.b16 {%0,%1,%2,%3}, [%4];"
                 : "=r"(r[0]), "=r"(r[1]), "=r"(r[2]), "=r"(r[3]) : "r"(addr));
}
__device__ __forceinline__ void mma16816(float* c, const uint32_t* a,
                                         uint32_t b0, uint32_t b1) {
    asm volatile(
        "mma.sync.aligned.m16n8k16.row.col.f32.f16.f16.f32 "
        "{%0,%1,%2,%3}, {%4,%5,%6,%7}, {%8,%9}, {%0,%1,%2,%3};"
        : "+f"(c[0]), "+f"(c[1]), "+f"(c[2]), "+f"(c[3])
        : "r"(a[0]), "r"(a[1]), "r"(a[2]), "r"(a[3]), "r"(b0), "r"(b1));
}
__device__ __forceinline__ void cp16(uint32_t dst, const void* src) {
    asm volatile("cp.async.cg.shared.global [%0], [%1], 16;"
                 :: "r"(dst), "l"(src) : "memory");
}
#define CP_COMMIT() asm volatile("cp.async.commit_group;" ::: "memory")
#define CP_WAIT1()  asm volatile("cp.async.wait_group 1;"  ::: "memory")

// ---------------------------------------------------------------------------
// Kernel 1: g_bf[n][k] = fp16( (features @ W)[k][n] )   — fused transpose.
// ---------------------------------------------------------------------------
__global__ __launch_bounds__(256) void lin_kernel(
    const float* __restrict__ F, const float* __restrict__ W)
{
    __shared__ float Ws[IN_CH][OUT_CH];
    const int tid = threadIdx.x;
    #pragma unroll
    for (int t = 0; t < 8; t++) {
        int idx = tid + t * 256;
        int r = idx >> 4, c4 = idx & 15;
        *reinterpret_cast<float4*>(&Ws[r][c4 * 4]) =
            *reinterpret_cast<const float4*>(&W[r * OUT_CH + c4 * 4]);
    }
    __syncthreads();

    const int row = blockIdx.x * 32 + (tid >> 3);
    const int c0  = (tid & 7) * 8;
    float acc[8];
    #pragma unroll
    for (int j = 0; j < 8; j++) acc[j] = 0.0f;

    #pragma unroll 8
    for (int k = 0; k < IN_CH; k += 4) {
        float4 a4 = *reinterpret_cast<const float4*>(&F[row * IN_CH + k]);
        float av[4] = {a4.x, a4.y, a4.z, a4.w};
        #pragma unroll
        for (int kk = 0; kk < 4; kk++)
            #pragma unroll
            for (int j = 0; j < 8; j++)
                acc[j] = fmaf(av[kk], Ws[k + kk][c0 + j], acc[j]);
    }
    #pragma unroll
    for (int j = 0; j < 8; j++)
        g_bf[(size_t)(c0 + j) * N_DIM + row] = __float2half(acc[j]);
}

// ---------------------------------------------------------------------------
// Kernel 2: fp16 GEMM (mma.sync.m16n8k16), cp.async 2-deep fp32 landing ring,
//           bulk convert pass, R10 swizzled fp16 consume path.
//   partial[s] = A[mTile, kspan_s] @ B^T      (B from g_bf)
// ---------------------------------------------------------------------------

// Issue A chunk u into landing[u&1] (4 x cp.async 16B per thread)
#define ISSUE_A(u_) do {                                                        \
    uint32_t fd_ = sbase + (uint32_t)((u_) & 1) * F_STAGE + (uint32_t)tid * 80; \
    _Pragma("unroll")                                                           \
    for (int j_ = 0; j_ < 4; j_++)                                              \
        cp16(fd_ + j_ * 16, Ap + (u_) * KB + j_ * 4);                           \
} while (0)

// Convert landing[u&1] (own 64B slot) -> fp16 A region of stage[u&1]
#define CONVERT_A(u_) do {                                                      \
    const char* lp_ = sm + ((u_) & 1) * F_STAGE + tid * 80;                     \
    char* sb_ = sm + H_BASE + ((u_) & 1) * H_STRIDE;                            \
    _Pragma("unroll")                                                           \
    for (int i_ = 0; i_ < 2; i_++) {                                            \
        float4 va_ = *reinterpret_cast<const float4*>(lp_ + i_ * 32);           \
        float4 vb_ = *reinterpret_cast<const float4*>(lp_ + i_ * 32 + 16);      \
        uint4 h_;                                                               \
        asm("cvt.rn.f16x2.f32 %0, %1, %2;" : "=r"(h_.x) : "f"(va_.y), "f"(va_.x)); \
        asm("cvt.rn.f16x2.f32 %0, %1, %2;" : "=r"(h_.y) : "f"(va_.w), "f"(va_.z)); \
        asm("cvt.rn.f16x2.f32 %0, %1, %2;" : "=r"(h_.z) : "f"(vb_.y), "f"(vb_.x)); \
        asm("cvt.rn.f16x2.f32 %0, %1, %2;" : "=r"(h_.w) : "f"(vb_.w), "f"(vb_.z)); \
        uint32_t c_   = (uint32_t)(aH * 2 + i_);                                \
        uint32_t off_ = (uint32_t)aR * 64 + ((c_ ^ aXor) << 4);                 \
        *reinterpret_cast<uint4*>(sb_ + ST_A + off_) = h_;                      \
    }                                                                           \
} while (0)

__global__ __launch_bounds__(GTHREADS, 3) void mma_gemm(const float* __restrict__ A)
{
    extern __shared__ __align__(128) char sm[];
    const uint32_t sbase = smem_u32(sm);

    const int tid = threadIdx.x;
    const int wid = tid >> 5;
    const int lid = tid & 31;
    const int wm  = wid * 16;                 // warp's 16-row slice

    const int mBase = blockIdx.x * TM;
    const int kBase = blockIdx.y * KSPAN;

    // A cp.async coords: row aR = tid>>1, half aH = tid&1 (16 floats)
    const int aR = tid >> 1;
    const int aH = tid & 1;
    const uint32_t aXor = (uint32_t)((aR >> 1) & 3);
    // B staging: row = tid>>2 (0..63), 16B chunk = tid&3
    const int bRow = tid >> 2;
    const int bC   = tid & 3;
    const uint32_t bDst = (uint32_t)bRow * 64 +
                          (((uint32_t)bC ^ (uint32_t)((bRow >> 1) & 3)) << 4);

    const float*  Ap = A + (size_t)(mBase + aR) * N_DIM + kBase + aH * 16;
    const __half* Bp = g_bf + (size_t)bRow * N_DIM + kBase + bC * 8;

    // per-lane ldmatrix invariants (R10-proven)
    const uint32_t rA    = (uint32_t)(wm + (lid & 15));
    const uint32_t aFXor = (rA >> 1) & 3u;
    const uint32_t aRowB = rA * 64u;
    const uint32_t aSel  = (uint32_t)(lid >> 4);
    const uint32_t rBL   = (uint32_t)((lid & 7) + ((lid >> 4) & 1) * 8);
    const uint32_t bFXor = (rBL >> 1) & 3u;
    const uint32_t bSel  = (uint32_t)((lid >> 3) & 1);

    float acc[8][4];
    #pragma unroll
    for (int t = 0; t < 8; t++)
        #pragma unroll
        for (int j = 0; j < 4; j++) acc[t][j] = 0.0f;

    uint4 bReg;

    // ---- prologue: A(0), A(1) in flight; stage0 built ----
    ISSUE_A(0); CP_COMMIT();
    ISSUE_A(1); CP_COMMIT();
    bReg = *reinterpret_cast<const uint4*>(Bp);
    CP_WAIT1();                               // A(0) landed
    CONVERT_A(0);
    *reinterpret_cast<uint4*>(sm + H_BASE + ST_B + bDst) = bReg;
    __syncthreads();

    for (int it = 0; it < NITER; it++) {
        // top: issue A(it+2) (2 iters of slack), prefetch B(it+1)
        if (it + 2 < NITER) ISSUE_A(it + 2);
        CP_COMMIT();                          // always (possibly empty group)
        if (it + 1 < NITER)
            bReg = *reinterpret_cast<const uint4*>(Bp + (it + 1) * KB);

        // compute from stage[it&1]
        const uint32_t so = sbase + H_BASE + (uint32_t)(it & 1) * H_STRIDE;
        #pragma unroll
        for (int ks = 0; ks < 2; ks++) {
            uint32_t a[4];
            {
                uint32_t aOff = (((uint32_t)(ks * 2) + aSel) ^ aFXor) << 4;
                ldsm4(a, so + ST_A + aRowB + aOff);
            }
            uint32_t bOff = (((uint32_t)(ks * 2) + bSel) ^ bFXor) << 4;
            #pragma unroll
            for (int np = 0; np < 4; np++) {
                uint32_t bAddr = so + ST_B + (uint32_t)np * 1024 + rBL * 64 + bOff;
                uint32_t b[4];
                ldsm4(b, bAddr);
                mma16816(acc[np * 2],     a, b[0], b[1]);
                mma16816(acc[np * 2 + 1], a, b[2], b[3]);
            }
        }

        // bottom: A(it+1) is landed (newest group may stay in flight)
        if (it + 1 < NITER) {
            CP_WAIT1();
            CONVERT_A(it + 1);
            *reinterpret_cast<uint4*>(
                sm + H_BASE + ((it + 1) & 1) * H_STRIDE + ST_B + bDst) = bReg;
        }
        __syncthreads();
    }

    // ---- epilogue (R10-proven c-fragment layout) ----
    const int g  = lid >> 2;
    const int tg = lid & 3;
    float* part = g_part + (size_t)blockIdx.y * (N_DIM * OUT_CH);
    const int row0 = mBase + wm + g;
    #pragma unroll
    for (int t = 0; t < 8; t++) {
        int col = t * 8 + tg * 2;
        *reinterpret_cast<float2*>(&part[(size_t)row0 * OUT_CH + col]) =
            make_float2(acc[t][0], acc[t][1]);
        *reinterpret_cast<float2*>(&part[(size_t)(row0 + 8) * OUT_CH + col]) =
            make_float2(acc[t][2], acc[t][3]);
    }
}

// ---------------------------------------------------------------------------
// Kernel 3: reduce split-K partials.
//   phase 0: g_bf[n][m] = fp16( filt[m] * sum_s P[s][m][n] )  (fused transpose)
//   phase 1: d_out      = sum_s P[s]
// ---------------------------------------------------------------------------
__global__ __launch_bounds__(256) void reduce_kernel(
    const float* __restrict__ filt, float* __restrict__ outp, int phase)
{
    const int i = blockIdx.x * blockDim.x + threadIdx.x;
    const int stride4 = (N_DIM * OUT_CH) / 4;
    const float4* P = reinterpret_cast<const float4*>(g_part);

    float4 s = P[i];
    #pragma unroll
    for (int sp = 1; sp < SPLITK; sp++) {
        float4 v = P[i + sp * stride4];
        s.x += v.x; s.y += v.y; s.z += v.z; s.w += v.w;
    }
    if (phase == 0) {
        int m = (i * 4) / OUT_CH;
        int c = (i * 4) % OUT_CH;
        float f = filt[m];
        g_bf[(size_t)(c + 0) * N_DIM + m] = __float2half(s.x * f);
        g_bf[(size_t)(c + 1) * N_DIM + m] = __float2half(s.y * f);
        g_bf[(size_t)(c + 2) * N_DIM + m] = __float2half(s.z * f);
        g_bf[(size_t)(c + 3) * N_DIM + m] = __float2half(s.w * f);
    } else {
        reinterpret_cast<float4*>(outp)[i] = s;
    }
}

// ---------------------------------------------------------------------------
// Launch. Inputs: features, weight_matrix, filt, wavelets, wavelets_inv.
// ---------------------------------------------------------------------------
extern "C" void kernel_launch(void* const* d_in, const int* in_sizes, int n_in,
                              void* d_out, int out_size)
{
    const float* features     = (const float*)d_in[0];
    const float* weight       = (const float*)d_in[1];
    const float* filt         = (const float*)d_in[2];
    const float* wavelets     = (const float*)d_in[3];
    const float* wavelets_inv = (const float*)d_in[4];
    float* out = (float*)d_out;

    cudaFuncSetAttribute(mma_gemm,
                         cudaFuncAttributeMaxDynamicSharedMemorySize, DSMEM);

    dim3 grid(N_DIM / TM, SPLITK);                      // (64, 16)
    const int redBlocks = (N_DIM * OUT_CH) / 4 / 256;   // 512

    lin_kernel<<<N_DIM / 32, 256>>>(features, weight);
    mma_gemm<<<grid, GTHREADS, DSMEM>>>(wavelets_inv);
    reduce_kernel<<<redBlocks, 256>>>(filt, nullptr, 0);
    mma_gemm<<<grid, GTHREADS, DSMEM>>>(wavelets);
    reduce_kernel<<<redBlocks, 256>>>(filt, out, 1);
}